// round 5
// baseline (speedup 1.0000x reference)
#include <cuda_runtime.h>
#include <cuda_bf16.h>
#include <math.h>

// ---------------- problem constants ----------------
#define Bb 16
#define NH 8
#define BH (Bb*NH)          // 128
#define Hh 56
#define Ww 56
#define Nn (Hh*Ww)          // 3136
#define HD 64
#define RATIO 4
#define HL (Hh/RATIO)       // 14
#define MM (HL*HL)          // 196 landmarks
#define PATCH (RATIO*RATIO*HD) // 1024
#define NEWTON_ITERS 20
#define LN_EPS 1e-5f
#define QSCALE 0.35355339059327373f   // 64^{-0.25}

typedef unsigned long long u64;

// ---------------- device scratch ----------------
__device__ float g_Qs   [(size_t)BH*Nn*HD];
__device__ float g_qn   [(size_t)BH*Nn];
__device__ float g_patch[(size_t)BH*MM*PATCH];
__device__ float g_Ql   [(size_t)BH*MM*HD];
__device__ float g_QlT  [(size_t)BH*HD*MM];
__device__ float g_ln   [(size_t)BH*MM];
__device__ float g_k2   [(size_t)BH*MM*MM];
__device__ float g_scale[BH];
__device__ float g_Va   [(size_t)BH*MM*MM];
__device__ float g_Vb   [(size_t)BH*MM*MM];
__device__ float g_T    [(size_t)BH*MM*MM];
__device__ float g_k1   [(size_t)BH*Nn*MM];
__device__ float g_Z    [(size_t)BH*MM*HD];
__device__ float g_Y    [(size_t)BH*MM*HD];

// ---------------- packed f32x2 helpers ----------------
__device__ __forceinline__ u64 fma2(u64 a, u64 b, u64 c) {
    u64 d;
    asm("fma.rn.f32x2 %0, %1, %2, %3;" : "=l"(d) : "l"(a), "l"(b), "l"(c));
    return d;
}
__device__ __forceinline__ u64 dup2(float x) {
    u64 r;
    asm("mov.b64 %0, {%1, %1};" : "=l"(r) : "f"(x));
    return r;
}
__device__ __forceinline__ float2 unpk(u64 v) {
    float2 r;
    asm("mov.b64 {%0, %1}, %2;" : "=f"(r.x), "=f"(r.y) : "l"(v));
    return r;
}

// ---------------- kernel 1: Qs = Q*s, qn = |row|^2 ----------------
__global__ __launch_bounds__(256) void scale_qnorm_kernel(const float* __restrict__ Q,
                                                          float* __restrict__ Qs,
                                                          float* __restrict__ qn) {
    size_t warp = ((size_t)blockIdx.x * blockDim.x + threadIdx.x) >> 5;
    int lane = threadIdx.x & 31;
    if (warp >= (size_t)BH * Nn) return;
    float2 v = ((const float2*)(Q + warp * HD))[lane];
    v.x *= QSCALE; v.y *= QSCALE;
    ((float2*)(Qs + warp * HD))[lane] = v;
    float ss = v.x * v.x + v.y * v.y;
    #pragma unroll
    for (int o = 16; o; o >>= 1) ss += __shfl_xor_sync(0xffffffffu, ss, o);
    if (lane == 0) qn[warp] = ss;
}

// ---------------- kernel 2: im2col ----------------
__global__ __launch_bounds__(256) void im2col_kernel(const float* __restrict__ Qs,
                                                     float* __restrict__ patch) {
    size_t idx = (size_t)blockIdx.x * blockDim.x + threadIdx.x;
    const size_t total = (size_t)BH * MM * PATCH;
    if (idx >= total) return;
    int ic = idx & (HD - 1);
    int e  = (int)((idx >> 6) & 15);
    size_t row = idx >> 10;
    int p  = (int)(row % MM);
    int bh = (int)(row / MM);
    int py = p / HL, px = p % HL;
    int dy = e >> 2, dx = e & 3;
    int y = py * RATIO + dy, x = px * RATIO + dx;
    patch[idx] = Qs[((size_t)bh * Nn + (size_t)y * Ww + x) * HD + ic];
}

// ---------------- packed-f32x2 batched SGEMM ----------------
// EPI: 0 C=AB, 1 C=exp(-0.5(r[i]+c[j]-2AB)), 2 C=2A-AB (A square, lda==ldc), 3 C+=AB
// TRA: 0 A [M,K]; 1 A stored [K,M] -> compute A^T B
template<int EPI, int TRA, int TM, int TN, int TY, int TX>
__global__ __launch_bounds__(TY*TX) void gemm2_kernel(const float* __restrict__ A,
                                                      const float* __restrict__ B,
                                                      float* __restrict__ C,
                                                      const float* __restrict__ rAux,
                                                      const float* __restrict__ cAux,
                                                      int M, int N, int K,
                                                      int lda, int ldb, int ldc,
                                                      size_t sA, size_t sB, size_t sC,
                                                      int sRA, int sCA) {
    constexpr int BM = TY * TM;
    constexpr int BN = TX * TN;
    constexpr int BK = 16;
    constexpr int NT = TY * TX;
    constexpr int BMP = BM + 2;   // pad keeps 8B align, avoids transpose conflicts

    int bz = blockIdx.z;
    A += (size_t)bz * sA; B += (size_t)bz * sB; C += (size_t)bz * sC;
    if (EPI == 1) { rAux += (size_t)bz * sRA; cAux += (size_t)bz * sCA; }

    int m0 = blockIdx.y * BM, n0 = blockIdx.x * BN;
    int tid = threadIdx.x;
    int ty = tid / TX, tx = tid % TX;
    int mr = ty * TM;
    int nr = tx * TN;

    __shared__ __align__(16) float As[BK][BMP];
    __shared__ __align__(16) u64  Bs[BK][BN];

    u64 acc[TM/2][TN];
    #pragma unroll
    for (int p = 0; p < TM/2; p++)
        #pragma unroll
        for (int j = 0; j < TN; j++) acc[p][j] = 0ull;

    for (int k0 = 0; k0 < K; k0 += BK) {
        for (int idx = tid; idx < BM * BK; idx += NT) {
            int kk, mmL;
            if (TRA == 0) { mmL = idx / BK; kk = idx % BK; }
            else          { kk = idx / BM; mmL = idx % BM; }
            int gm = m0 + mmL, gk = k0 + kk;
            float v = 0.f;
            if (gm < M && gk < K)
                v = (TRA == 0) ? A[(size_t)gm * lda + gk] : A[(size_t)gk * lda + gm];
            As[kk][mmL] = v;
        }
        for (int idx = tid; idx < BN * BK; idx += NT) {
            int kk = idx / BN, nn = idx % BN;
            int gk = k0 + kk, gn = n0 + nn;
            float v = (gk < K && gn < N) ? B[(size_t)gk * ldb + gn] : 0.f;
            Bs[kk][nn] = dup2(v);
        }
        __syncthreads();
        #pragma unroll
        for (int kk = 0; kk < BK; kk++) {
            u64 a[TM/2];
            #pragma unroll
            for (int p = 0; p < TM/2; p++)
                a[p] = *(const u64*)&As[kk][mr + 2*p];
            u64 b[TN];
            #pragma unroll
            for (int j = 0; j < TN; j++) b[j] = Bs[kk][nr + j];
            #pragma unroll
            for (int p = 0; p < TM/2; p++)
                #pragma unroll
                for (int j = 0; j < TN; j++)
                    acc[p][j] = fma2(a[p], b[j], acc[p][j]);
        }
        __syncthreads();
    }

    #pragma unroll
    for (int p = 0; p < TM/2; p++) {
        int gm0 = m0 + mr + 2*p;
        #pragma unroll
        for (int j = 0; j < TN; j++) {
            int gn = n0 + nr + j;
            if (gn >= N) continue;
            float2 v2 = unpk(acc[p][j]);
            #pragma unroll
            for (int h = 0; h < 2; h++) {
                int gm = gm0 + h;
                if (gm >= M) continue;
                float v = h ? v2.y : v2.x;
                size_t off = (size_t)gm * ldc + gn;
                if (EPI == 0)      C[off] = v;
                else if (EPI == 1) C[off] = __expf(-0.5f * (rAux[gm] + cAux[gn] - 2.f * v));
                else if (EPI == 2) C[off] = 2.f * A[(size_t)gm * lda + gn] - v;
                else               C[off] += v;
            }
        }
    }
}

// ---------------- LayerNorm + erf-GELU + transpose + norms ----------------
__global__ __launch_bounds__(64) void ln_gelu_kernel(float* __restrict__ Ql,
                                                     float* __restrict__ QlT,
                                                     float* __restrict__ lnn,
                                                     const float* __restrict__ gamma,
                                                     const float* __restrict__ beta) {
    int row = blockIdx.x;
    int t = threadIdx.x;
    __shared__ float sm[2];
    float x = Ql[(size_t)row * HD + t];

    float v = x;
    #pragma unroll
    for (int o = 16; o; o >>= 1) v += __shfl_xor_sync(0xffffffffu, v, o);
    if ((t & 31) == 0) sm[t >> 5] = v;
    __syncthreads();
    float mean = (sm[0] + sm[1]) * (1.f / HD);
    __syncthreads();

    float d = x - mean;
    v = d * d;
    #pragma unroll
    for (int o = 16; o; o >>= 1) v += __shfl_xor_sync(0xffffffffu, v, o);
    if ((t & 31) == 0) sm[t >> 5] = v;
    __syncthreads();
    float var = (sm[0] + sm[1]) * (1.f / HD);
    __syncthreads();

    float y = d * rsqrtf(var + LN_EPS) * gamma[t] + beta[t];
    float g = 0.5f * y * (1.f + erff(y * 0.70710678118654752f));

    Ql[(size_t)row * HD + t] = g;
    int bh = row / MM, p = row % MM;
    QlT[((size_t)bh * HD + t) * MM + p] = g;

    v = g * g;
    #pragma unroll
    for (int o = 16; o; o >>= 1) v += __shfl_xor_sync(0xffffffffu, v, o);
    if ((t & 31) == 0) sm[t >> 5] = v;
    __syncthreads();
    if (t == 0) lnn[row] = sm[0] + sm[1];
}

// ---------------- Newton init scale ----------------
__global__ __launch_bounds__(256) void nscale_kernel(const float* __restrict__ k2,
                                                     float* __restrict__ scale) {
    int bh = blockIdx.x;
    int t = threadIdx.x;
    float rs = 0.f;
    if (t < MM) {
        const float* r = k2 + (size_t)bh * MM * MM + (size_t)t * MM;
        for (int j = 0; j < MM; j++) rs += r[j];
    }
    __shared__ float sm[256];
    sm[t] = rs;
    __syncthreads();
    for (int o = 128; o; o >>= 1) {
        if (t < o) sm[t] = fmaxf(sm[t], sm[t + o]);
        __syncthreads();
    }
    if (t == 0) scale[bh] = 1.f / (sm[0] * sm[0]);
}

__global__ __launch_bounds__(256) void v0_kernel(const float* __restrict__ k2,
                                                 const float* __restrict__ scale,
                                                 float* __restrict__ V0) {
    size_t i = (size_t)blockIdx.x * blockDim.x + threadIdx.x;
    const size_t total = (size_t)BH * MM * MM;
    if (i >= total) return;
    V0[i] = k2[i] * scale[i / ((size_t)MM * MM)];
}

// ---------------- depthwise 3x3 conv over heads ----------------
__global__ __launch_bounds__(256) void dwconv_kernel(const float* __restrict__ V,
                                                     const float* __restrict__ w,
                                                     float* __restrict__ out) {
    int bh = blockIdx.y;
    int y  = blockIdx.x;
    int h  = bh & (NH - 1);
    float wv[9];
    #pragma unroll
    for (int k = 0; k < 9; k++) wv[k] = w[k * NH + h];
    for (int idx = threadIdx.x; idx < Ww * HD; idx += blockDim.x) {
        int x = idx >> 6;
        int c = idx & (HD - 1);
        float acc = 0.f;
        #pragma unroll
        for (int dy = -1; dy <= 1; dy++) {
            int yy = y + dy;
            if (yy < 0 || yy >= Hh) continue;
            #pragma unroll
            for (int dx = -1; dx <= 1; dx++) {
                int xx = x + dx;
                if (xx < 0 || xx >= Ww) continue;
                acc += wv[(dy + 1) * 3 + (dx + 1)] *
                       V[((size_t)bh * Nn + (size_t)yy * Ww + xx) * HD + c];
            }
        }
        out[((size_t)bh * Nn + (size_t)y * Ww + x) * HD + c] = acc;
    }
}

// ---------------- host launch ----------------
static inline int ceil_div(int a, int b) { return (a + b - 1) / b; }

// WIDE: BM=112, BN=112, 224 threads
#define WIDE_ARGS 8, 7, 14, 16
// SKIN: BM=112, BN=64, 224 threads
#define SKIN_ARGS 4, 8, 28, 8

extern "C" void kernel_launch(void* const* d_in, const int* in_sizes, int n_in,
                              void* d_out, int out_size) {
    const float* Q      = (const float*)d_in[0];
    const float* V      = (const float*)d_in[1];
    const float* w_land = (const float*)d_in[2];
    const float* gamma  = (const float*)d_in[3];
    const float* beta   = (const float*)d_in[4];
    const float* conv_w = (const float*)d_in[5];
    float* out = (float*)d_out;

    float *Qs, *qn, *patch, *Ql, *QlT, *lnn, *k2, *scale, *Va, *Vb, *T, *k1, *Z, *Y;
    cudaGetSymbolAddress((void**)&Qs,    g_Qs);
    cudaGetSymbolAddress((void**)&qn,    g_qn);
    cudaGetSymbolAddress((void**)&patch, g_patch);
    cudaGetSymbolAddress((void**)&Ql,    g_Ql);
    cudaGetSymbolAddress((void**)&QlT,   g_QlT);
    cudaGetSymbolAddress((void**)&lnn,   g_ln);
    cudaGetSymbolAddress((void**)&k2,    g_k2);
    cudaGetSymbolAddress((void**)&scale, g_scale);
    cudaGetSymbolAddress((void**)&Va,    g_Va);
    cudaGetSymbolAddress((void**)&Vb,    g_Vb);
    cudaGetSymbolAddress((void**)&T,     g_T);
    cudaGetSymbolAddress((void**)&k1,    g_k1);
    cudaGetSymbolAddress((void**)&Z,     g_Z);
    cudaGetSymbolAddress((void**)&Y,     g_Y);

    // 1) scale + row norms
    {
        size_t rows = (size_t)BH * Nn;
        int blocks = (int)((rows * 32 + 255) / 256);
        scale_qnorm_kernel<<<blocks, 256>>>(Q, Qs, qn);
    }
    // 2) im2col
    {
        size_t total = (size_t)BH * MM * PATCH;
        im2col_kernel<<<(int)((total + 255) / 256), 256>>>(Qs, patch);
    }
    // 3) landmark conv GEMM: [25088,1024]x[1024,64]
    {
        dim3 grid(1, 25088 / 112, 1);
        gemm2_kernel<0, 0, SKIN_ARGS><<<grid, 224>>>(patch, w_land, Ql, nullptr, nullptr,
                                                     BH * MM, HD, PATCH, PATCH, HD, HD,
                                                     0, 0, 0, 0, 0);
    }
    // 4) LN + GELU + transpose + norms
    ln_gelu_kernel<<<BH * MM, 64>>>(Ql, QlT, lnn, gamma, beta);
    // 5) k2 = gauss(Ql,Ql)
    {
        dim3 grid(2, 2, BH);
        gemm2_kernel<1, 0, WIDE_ARGS><<<grid, 224>>>(Ql, QlT, k2, lnn, lnn,
                                                     MM, MM, HD, HD, MM, MM,
                                                     (size_t)MM * HD, (size_t)HD * MM, (size_t)MM * MM,
                                                     MM, MM);
    }
    // 6) Newton init
    nscale_kernel<<<BH, 256>>>(k2, scale);
    {
        size_t total = (size_t)BH * MM * MM;
        v0_kernel<<<(int)((total + 255) / 256), 256>>>(k2, scale, Va);
    }
    // 7) Newton-Schulz iterations
    {
        dim3 grid(2, 2, BH);
        float* cur = Va;
        float* nxt = Vb;
        for (int it = 0; it < NEWTON_ITERS; it++) {
            gemm2_kernel<0, 0, WIDE_ARGS><<<grid, 224>>>(k2, cur, T, nullptr, nullptr,
                                                         MM, MM, MM, MM, MM, MM,
                                                         (size_t)MM * MM, (size_t)MM * MM, (size_t)MM * MM,
                                                         0, 0);
            gemm2_kernel<2, 0, WIDE_ARGS><<<grid, 224>>>(cur, T, nxt, nullptr, nullptr,
                                                         MM, MM, MM, MM, MM, MM,
                                                         (size_t)MM * MM, (size_t)MM * MM, (size_t)MM * MM,
                                                         0, 0);
            float* tmp = cur; cur = nxt; nxt = tmp;
        }
    }
    // 8) k1 = gauss(Qs, Ql): [3136,64]x[64,196]
    {
        dim3 grid(2, Nn / 112, BH);
        gemm2_kernel<1, 0, WIDE_ARGS><<<grid, 224>>>(Qs, QlT, k1, qn, lnn,
                                                     Nn, MM, HD, HD, MM, MM,
                                                     (size_t)Nn * HD, (size_t)HD * MM, (size_t)Nn * MM,
                                                     Nn, MM);
    }
    // 9) Z = k1^T @ V
    {
        dim3 grid(1, 2, BH);
        gemm2_kernel<0, 1, SKIN_ARGS><<<grid, 224>>>(k1, V, Z, nullptr, nullptr,
                                                     MM, HD, Nn, MM, HD, HD,
                                                     (size_t)Nn * MM, (size_t)Nn * HD, (size_t)MM * HD,
                                                     0, 0);
    }
    // 10) Y = inv @ Z
    {
        dim3 grid(1, 2, BH);
        gemm2_kernel<0, 0, SKIN_ARGS><<<grid, 224>>>(Va, Z, Y, nullptr, nullptr,
                                                     MM, HD, MM, MM, HD, HD,
                                                     (size_t)MM * MM, (size_t)MM * HD, (size_t)MM * HD,
                                                     0, 0);
    }
    // 11) depthwise conv residual -> d_out
    {
        dim3 grid(Hh, BH);
        dwconv_kernel<<<grid, 256>>>(V, conv_w, out);
    }
    // 12) d_out += k1 @ Y
    {
        dim3 grid(1, Nn / 112, BH);
        gemm2_kernel<3, 0, SKIN_ARGS><<<grid, 224>>>(k1, Y, out, nullptr, nullptr,
                                                     Nn, HD, MM, MM, HD, HD,
                                                     (size_t)Nn * MM, (size_t)MM * HD, (size_t)Nn * HD,
                                                     0, 0);
    }
    (void)in_sizes; (void)n_in; (void)out_size;
}

// round 8
// speedup vs baseline: 1.1568x; 1.1568x over previous
#include <cuda_runtime.h>
#include <cuda_bf16.h>
#include <math.h>
#include <stdint.h>

// ---------------- problem constants ----------------
#define Bb 16
#define NH 8
#define BH (Bb*NH)          // 128
#define Hh 56
#define Ww 56
#define Nn (Hh*Ww)          // 3136
#define HD 64
#define RATIO 4
#define HL (Hh/RATIO)       // 14
#define MM (HL*HL)          // 196 landmarks
#define PATCH (RATIO*RATIO*HD) // 1024
#define NEWTON_ITERS 20
#define CHEAP_ITERS 16      // single-pass bf16 iterations; rest 3-pass split
#define LN_EPS 1e-5f
#define QSCALE 0.35355339059327373f   // 64^{-0.25}

#define PD 256              // padded Newton dim
#define PD2 ((size_t)PD*PD)

typedef unsigned long long u64;
typedef unsigned int u32;

// ---------------- device scratch ----------------
__device__ float g_Qs   [(size_t)BH*Nn*HD];
__device__ float g_qn   [(size_t)BH*Nn];
__device__ float g_patch[(size_t)BH*MM*PATCH];
__device__ float g_Ql   [(size_t)BH*MM*HD];
__device__ float g_QlT  [(size_t)BH*HD*MM];
__device__ float g_ln   [(size_t)BH*MM];
__device__ float g_k2   [(size_t)BH*MM*MM];
__device__ float g_scale[BH];
__device__ float g_Va   [(size_t)BH*MM*MM];   // merged inverse (fp32)
__device__ float g_k1   [(size_t)BH*Nn*MM];
__device__ float g_Z    [(size_t)BH*MM*HD];
__device__ float g_Y    [(size_t)BH*MM*HD];

// split bf16 Newton state, all [BH][256][256]
__device__ __nv_bfloat16 g_Phi [(size_t)BH*PD2], g_Plo [(size_t)BH*PD2];
__device__ __nv_bfloat16 g_VAh [(size_t)BH*PD2], g_VAl [(size_t)BH*PD2];
__device__ __nv_bfloat16 g_VtAh[(size_t)BH*PD2], g_VtAl[(size_t)BH*PD2];
__device__ __nv_bfloat16 g_VBh [(size_t)BH*PD2], g_VBl [(size_t)BH*PD2];
__device__ __nv_bfloat16 g_VtBh[(size_t)BH*PD2], g_VtBl[(size_t)BH*PD2];
__device__ __nv_bfloat16 g_Tth [(size_t)BH*PD2], g_Ttl [(size_t)BH*PD2];

__device__ __forceinline__ void split2(float x, __nv_bfloat16& h, __nv_bfloat16& l) {
    h = __float2bfloat16(x);
    l = __float2bfloat16(x - __bfloat162float(h));
}

// ---------------- warp mma.sync m16n8k16 bf16 ----------------
__device__ __forceinline__ void mma16816(float* c, const u32* a, const u32* b) {
    asm volatile(
        "mma.sync.aligned.m16n8k16.row.col.f32.bf16.bf16.f32 "
        "{%0,%1,%2,%3}, {%4,%5,%6,%7}, {%8,%9}, {%0,%1,%2,%3};"
        : "+f"(c[0]), "+f"(c[1]), "+f"(c[2]), "+f"(c[3])
        : "r"(a[0]), "r"(a[1]), "r"(a[2]), "r"(a[3]), "r"(b[0]), "r"(b[1]));
}

// ======== Newton tensor-core GEMM via mma.sync ========
// All operands row-major [256][256] bf16 (B operand is [n][k], i.e. transposed logical).
// D[m][n] = sum_k A[m][k] * B[n][k]  (+ split cross terms if NPASS==3)
// MODE 0: store O1[n][m] = 2*I[m][n] - D[m][n]  (split hi/lo)   [T' transposed]
// MODE 1: store O1[m][n] = D (split), O2[n][m] = D (split)      [V' row + transposed]
#define SKA 40   // smem row stride (halves), conflict-free for fragment loads
template<int NPASS, int MODE>
__global__ __launch_bounds__(256, 1)
void newton_wmma_kernel(const __nv_bfloat16* __restrict__ Ahi,
                        const __nv_bfloat16* __restrict__ Alo,
                        const __nv_bfloat16* __restrict__ Bhi,
                        const __nv_bfloat16* __restrict__ Blo,
                        __nv_bfloat16* __restrict__ O1hi,
                        __nv_bfloat16* __restrict__ O1lo,
                        __nv_bfloat16* __restrict__ O2hi,
                        __nv_bfloat16* __restrict__ O2lo) {
    __shared__ __align__(16) __nv_bfloat16 Ah_s[128][SKA];
    __shared__ __align__(16) __nv_bfloat16 Bh_s[128][SKA];
    __shared__ __align__(16) __nv_bfloat16 Al_s[128][SKA];
    __shared__ __align__(16) __nv_bfloat16 Bl_s[128][SKA];

    const int bh = blockIdx.z;
    const size_t base = (size_t)bh * PD2;
    const int m0 = blockIdx.y * 128, n0 = blockIdx.x * 128;

    const int tid  = threadIdx.x;
    const int wid  = tid >> 5, lane = tid & 31;
    const int wm   = wid >> 2, wn = wid & 3;       // 2x4 warp grid
    const int gid  = lane >> 2, tig = lane & 3;

    float acc[4][4][4];
    #pragma unroll
    for (int mt = 0; mt < 4; mt++)
        #pragma unroll
        for (int nt = 0; nt < 4; nt++)
            #pragma unroll
            for (int i = 0; i < 4; i++) acc[mt][nt][i] = 0.f;

    const int r2 = tid >> 1;            // 0..127 row for tile loads
    const int hf = tid & 1;             // 0/1 half of 32-col chunk

    for (int kc = 0; kc < PD; kc += 32) {
        // global -> smem: A rows m0.., B rows n0.., 32 cols from kc
        #pragma unroll
        for (int j = 0; j < 4; j++) {
            int c = hf * 16 + j * 4;
            *(u64*)&Ah_s[r2][c] = *(const u64*)(Ahi + base + (size_t)(m0 + r2) * PD + kc + c);
            *(u64*)&Bh_s[r2][c] = *(const u64*)(Bhi + base + (size_t)(n0 + r2) * PD + kc + c);
            if (NPASS == 3) {
                *(u64*)&Al_s[r2][c] = *(const u64*)(Alo + base + (size_t)(m0 + r2) * PD + kc + c);
                *(u64*)&Bl_s[r2][c] = *(const u64*)(Blo + base + (size_t)(n0 + r2) * PD + kc + c);
            }
        }
        __syncthreads();

        #pragma unroll
        for (int k16 = 0; k16 < 2; k16++) {
            const int kb = k16 * 16;
            u32 af[4][4], bf[4][2];
            u32 alf[4][4], blf[4][2];
            #pragma unroll
            for (int mt = 0; mt < 4; mt++) {
                int r = wm * 64 + mt * 16 + gid;
                af[mt][0] = *(const u32*)&Ah_s[r    ][kb + tig * 2];
                af[mt][1] = *(const u32*)&Ah_s[r + 8][kb + tig * 2];
                af[mt][2] = *(const u32*)&Ah_s[r    ][kb + 8 + tig * 2];
                af[mt][3] = *(const u32*)&Ah_s[r + 8][kb + 8 + tig * 2];
                if (NPASS == 3) {
                    alf[mt][0] = *(const u32*)&Al_s[r    ][kb + tig * 2];
                    alf[mt][1] = *(const u32*)&Al_s[r + 8][kb + tig * 2];
                    alf[mt][2] = *(const u32*)&Al_s[r    ][kb + 8 + tig * 2];
                    alf[mt][3] = *(const u32*)&Al_s[r + 8][kb + 8 + tig * 2];
                }
            }
            #pragma unroll
            for (int nt = 0; nt < 4; nt++) {
                int r = wn * 32 + nt * 8 + gid;
                bf[nt][0] = *(const u32*)&Bh_s[r][kb + tig * 2];
                bf[nt][1] = *(const u32*)&Bh_s[r][kb + 8 + tig * 2];
                if (NPASS == 3) {
                    blf[nt][0] = *(const u32*)&Bl_s[r][kb + tig * 2];
                    blf[nt][1] = *(const u32*)&Bl_s[r][kb + 8 + tig * 2];
                }
            }
            #pragma unroll
            for (int mt = 0; mt < 4; mt++)
                #pragma unroll
                for (int nt = 0; nt < 4; nt++) {
                    mma16816(acc[mt][nt], af[mt], bf[nt]);
                    if (NPASS == 3) {
                        mma16816(acc[mt][nt], af[mt], blf[nt]);
                        mma16816(acc[mt][nt], alf[mt], bf[nt]);
                    }
                }
        }
        __syncthreads();
    }

    // epilogue
    #pragma unroll
    for (int mt = 0; mt < 4; mt++) {
        int gmb = m0 + wm * 64 + mt * 16;
        #pragma unroll
        for (int nt = 0; nt < 4; nt++) {
            int gnb = n0 + wn * 32 + nt * 8;
            #pragma unroll
            for (int i = 0; i < 4; i++) {
                int gm = gmb + gid + ((i >> 1) ? 8 : 0);
                int gn = gnb + tig * 2 + (i & 1);
                float v = acc[mt][nt][i];
                __nv_bfloat16 h, l;
                if (MODE == 0) {
                    float tp = ((gm == gn) ? 2.0f : 0.0f) - v;
                    split2(tp, h, l);
                    O1hi[base + (size_t)gn * PD + gm] = h;
                    O1lo[base + (size_t)gn * PD + gm] = l;
                } else {
                    split2(v, h, l);
                    O1hi[base + (size_t)gm * PD + gn] = h;
                    O1lo[base + (size_t)gm * PD + gn] = l;
                    O2hi[base + (size_t)gn * PD + gm] = h;
                    O2lo[base + (size_t)gn * PD + gm] = l;
                }
            }
        }
    }
}

// ======== prep: k2 -> padded split P, V0 (and Vt via symmetry) ========
__global__ __launch_bounds__(256) void newton_prep_kernel(const float* __restrict__ k2,
                                                          const float* __restrict__ scale,
                                                          __nv_bfloat16* __restrict__ Phi,
                                                          __nv_bfloat16* __restrict__ Plo,
                                                          __nv_bfloat16* __restrict__ Vh,
                                                          __nv_bfloat16* __restrict__ Vl,
                                                          __nv_bfloat16* __restrict__ Vth,
                                                          __nv_bfloat16* __restrict__ Vtl) {
    size_t idx = (size_t)blockIdx.x * blockDim.x + threadIdx.x;
    if (idx >= (size_t)BH * PD2) return;
    int bh = (int)(idx >> 16);
    int r = (int)((idx >> 8) & 255), c = (int)(idx & 255);
    float p = (r < MM && c < MM) ? k2[(size_t)bh * MM * MM + (size_t)r * MM + c] : 0.f;
    __nv_bfloat16 h, l;
    split2(p, h, l);
    Phi[idx] = h; Plo[idx] = l;
    float v0 = p * scale[bh];
    split2(v0, h, l);
    Vh[idx] = h;  Vl[idx] = l;
    Vth[idx] = h; Vtl[idx] = l;   // V0 symmetric
}

// ======== merge: split V -> fp32 inverse [196x196] ========
__global__ __launch_bounds__(256) void newton_merge_kernel(const __nv_bfloat16* __restrict__ Vh,
                                                           const __nv_bfloat16* __restrict__ Vl,
                                                           float* __restrict__ inv) {
    size_t idx = (size_t)blockIdx.x * blockDim.x + threadIdx.x;
    if (idx >= (size_t)BH * MM * MM) return;
    int bh = (int)(idx / ((size_t)MM * MM));
    int rem = (int)(idx % ((size_t)MM * MM));
    int r = rem / MM, c = rem % MM;
    size_t s = (size_t)bh * PD2 + (size_t)r * PD + c;
    inv[idx] = __bfloat162float(Vh[s]) + __bfloat162float(Vl[s]);
}

// ---------------- kernel: Qs = Q*s, qn = |row|^2 ----------------
__global__ __launch_bounds__(256) void scale_qnorm_kernel(const float* __restrict__ Q,
                                                          float* __restrict__ Qs,
                                                          float* __restrict__ qn) {
    size_t warp = ((size_t)blockIdx.x * blockDim.x + threadIdx.x) >> 5;
    int lane = threadIdx.x & 31;
    if (warp >= (size_t)BH * Nn) return;
    float2 v = ((const float2*)(Q + warp * HD))[lane];
    v.x *= QSCALE; v.y *= QSCALE;
    ((float2*)(Qs + warp * HD))[lane] = v;
    float ss = v.x * v.x + v.y * v.y;
    #pragma unroll
    for (int o = 16; o; o >>= 1) ss += __shfl_xor_sync(0xffffffffu, ss, o);
    if (lane == 0) qn[warp] = ss;
}

// ---------------- im2col ----------------
__global__ __launch_bounds__(256) void im2col_kernel(const float* __restrict__ Qs,
                                                     float* __restrict__ patch) {
    size_t idx = (size_t)blockIdx.x * blockDim.x + threadIdx.x;
    const size_t total = (size_t)BH * MM * PATCH;
    if (idx >= total) return;
    int ic = idx & (HD - 1);
    int e  = (int)((idx >> 6) & 15);
    size_t row = idx >> 10;
    int p  = (int)(row % MM);
    int bh = (int)(row / MM);
    int py = p / HL, px = p % HL;
    int dy = e >> 2, dx = e & 3;
    int y = py * RATIO + dy, x = px * RATIO + dx;
    patch[idx] = Qs[((size_t)bh * Nn + (size_t)y * Ww + x) * HD + ic];
}

// ---------------- scalar batched SGEMM ----------------
#define BMt 64
#define BNt 64
#define BKt 16
template<int EPI, int TRA>
__global__ __launch_bounds__(256) void gemm_kernel(const float* __restrict__ A,
                                                   const float* __restrict__ B,
                                                   float* __restrict__ C,
                                                   const float* __restrict__ rAux,
                                                   const float* __restrict__ cAux,
                                                   int M, int N, int K,
                                                   int lda, int ldb, int ldc,
                                                   size_t sA, size_t sB, size_t sC,
                                                   int sRA, int sCA) {
    int bz = blockIdx.z;
    A += (size_t)bz * sA; B += (size_t)bz * sB; C += (size_t)bz * sC;
    if (EPI == 1) { rAux += (size_t)bz * sRA; cAux += (size_t)bz * sCA; }
    int m0 = blockIdx.y * BMt, n0 = blockIdx.x * BNt;
    __shared__ float As[BKt][BMt];
    __shared__ float Bs[BKt][BNt];
    int t = threadIdx.x;
    int tx = t & 15, ty = t >> 4;
    float acc[4][4] = {};
    for (int k0 = 0; k0 < K; k0 += BKt) {
        #pragma unroll
        for (int j = 0; j < 4; j++) {
            int idx = t + 256 * j;
            if (TRA == 0) {
                int kk = idx & 15, mm = idx >> 4;
                int gm = m0 + mm, gk = k0 + kk;
                As[kk][mm] = (gm < M && gk < K) ? A[(size_t)gm * lda + gk] : 0.f;
            } else {
                int mm = idx & 63, kk = idx >> 6;
                int gm = m0 + mm, gk = k0 + kk;
                As[kk][mm] = (gm < M && gk < K) ? A[(size_t)gk * lda + gm] : 0.f;
            }
            int nn = idx & 63, kk2 = idx >> 6;
            int gn = n0 + nn, gk2 = k0 + kk2;
            Bs[kk2][nn] = (gn < N && gk2 < K) ? B[(size_t)gk2 * ldb + gn] : 0.f;
        }
        __syncthreads();
        #pragma unroll
        for (int kk = 0; kk < BKt; kk++) {
            float a[4], b[4];
            #pragma unroll
            for (int i = 0; i < 4; i++) a[i] = As[kk][ty * 4 + i];
            #pragma unroll
            for (int j = 0; j < 4; j++) b[j] = Bs[kk][tx * 4 + j];
            #pragma unroll
            for (int i = 0; i < 4; i++)
                #pragma unroll
                for (int j = 0; j < 4; j++)
                    acc[i][j] += a[i] * b[j];
        }
        __syncthreads();
    }
    #pragma unroll
    for (int i = 0; i < 4; i++) {
        int gm = m0 + ty * 4 + i;
        if (gm >= M) continue;
        #pragma unroll
        for (int j = 0; j < 4; j++) {
            int gn = n0 + tx * 4 + j;
            if (gn >= N) continue;
            float v = acc[i][j];
            size_t off = (size_t)gm * ldc + gn;
            if (EPI == 0)      C[off] = v;
            else if (EPI == 1) C[off] = __expf(-0.5f * (rAux[gm] + cAux[gn] - 2.f * v));
            else               C[off] += v;
        }
    }
}

// ---------------- LayerNorm + erf-GELU + transpose + norms ----------------
__global__ __launch_bounds__(64) void ln_gelu_kernel(float* __restrict__ Ql,
                                                     float* __restrict__ QlT,
                                                     float* __restrict__ lnn,
                                                     const float* __restrict__ gamma,
                                                     const float* __restrict__ beta) {
    int row = blockIdx.x;
    int t = threadIdx.x;
    __shared__ float sm[2];
    float x = Ql[(size_t)row * HD + t];

    float v = x;
    #pragma unroll
    for (int o = 16; o; o >>= 1) v += __shfl_xor_sync(0xffffffffu, v, o);
    if ((t & 31) == 0) sm[t >> 5] = v;
    __syncthreads();
    float mean = (sm[0] + sm[1]) * (1.f / HD);
    __syncthreads();

    float d = x - mean;
    v = d * d;
    #pragma unroll
    for (int o = 16; o; o >>= 1) v += __shfl_xor_sync(0xffffffffu, v, o);
    if ((t & 31) == 0) sm[t >> 5] = v;
    __syncthreads();
    float var = (sm[0] + sm[1]) * (1.f / HD);
    __syncthreads();

    float y = d * rsqrtf(var + LN_EPS) * gamma[t] + beta[t];
    float g = 0.5f * y * (1.f + erff(y * 0.70710678118654752f));

    Ql[(size_t)row * HD + t] = g;
    int bh = row / MM, p = row % MM;
    QlT[((size_t)bh * HD + t) * MM + p] = g;

    v = g * g;
    #pragma unroll
    for (int o = 16; o; o >>= 1) v += __shfl_xor_sync(0xffffffffu, v, o);
    if ((t & 31) == 0) sm[t >> 5] = v;
    __syncthreads();
    if (t == 0) lnn[row] = sm[0] + sm[1];
}

// ---------------- Newton init scale ----------------
__global__ __launch_bounds__(256) void nscale_kernel(const float* __restrict__ k2,
                                                     float* __restrict__ scale) {
    int bh = blockIdx.x;
    int t = threadIdx.x;
    float rs = 0.f;
    if (t < MM) {
        const float* r = k2 + (size_t)bh * MM * MM + (size_t)t * MM;
        for (int j = 0; j < MM; j++) rs += r[j];
    }
    __shared__ float sm[256];
    sm[t] = rs;
    __syncthreads();
    for (int o = 128; o; o >>= 1) {
        if (t < o) sm[t] = fmaxf(sm[t], sm[t + o]);
        __syncthreads();
    }
    if (t == 0) scale[bh] = 1.f / (sm[0] * sm[0]);
}

// ---------------- depthwise 3x3 conv over heads ----------------
__global__ __launch_bounds__(256) void dwconv_kernel(const float* __restrict__ V,
                                                     const float* __restrict__ w,
                                                     float* __restrict__ out) {
    int bh = blockIdx.y;
    int y  = blockIdx.x;
    int h  = bh & (NH - 1);
    float wv[9];
    #pragma unroll
    for (int k = 0; k < 9; k++) wv[k] = w[k * NH + h];
    for (int idx = threadIdx.x; idx < Ww * HD; idx += blockDim.x) {
        int x = idx >> 6;
        int c = idx & (HD - 1);
        float acc = 0.f;
        #pragma unroll
        for (int dy = -1; dy <= 1; dy++) {
            int yy = y + dy;
            if (yy < 0 || yy >= Hh) continue;
            #pragma unroll
            for (int dx = -1; dx <= 1; dx++) {
                int xx = x + dx;
                if (xx < 0 || xx >= Ww) continue;
                acc += wv[(dy + 1) * 3 + (dx + 1)] *
                       V[((size_t)bh * Nn + (size_t)yy * Ww + xx) * HD + c];
            }
        }
        out[((size_t)bh * Nn + (size_t)y * Ww + x) * HD + c] = acc;
    }
}

// ---------------- host launch ----------------
static inline int ceil_div(int a, int b) { return (a + b - 1) / b; }

extern "C" void kernel_launch(void* const* d_in, const int* in_sizes, int n_in,
                              void* d_out, int out_size) {
    const float* Q      = (const float*)d_in[0];
    const float* V      = (const float*)d_in[1];
    const float* w_land = (const float*)d_in[2];
    const float* gamma  = (const float*)d_in[3];
    const float* beta   = (const float*)d_in[4];
    const float* conv_w = (const float*)d_in[5];
    float* out = (float*)d_out;

    float *Qs, *qn, *patch, *Ql, *QlT, *lnn, *k2, *scale, *Va, *k1, *Z, *Y;
    cudaGetSymbolAddress((void**)&Qs,    g_Qs);
    cudaGetSymbolAddress((void**)&qn,    g_qn);
    cudaGetSymbolAddress((void**)&patch, g_patch);
    cudaGetSymbolAddress((void**)&Ql,    g_Ql);
    cudaGetSymbolAddress((void**)&QlT,   g_QlT);
    cudaGetSymbolAddress((void**)&lnn,   g_ln);
    cudaGetSymbolAddress((void**)&k2,    g_k2);
    cudaGetSymbolAddress((void**)&scale, g_scale);
    cudaGetSymbolAddress((void**)&Va,    g_Va);
    cudaGetSymbolAddress((void**)&k1,    g_k1);
    cudaGetSymbolAddress((void**)&Z,     g_Z);
    cudaGetSymbolAddress((void**)&Y,     g_Y);

    __nv_bfloat16 *Phi, *Plo, *VAh, *VAl, *VtAh, *VtAl, *VBh, *VBl, *VtBh, *VtBl, *Tth, *Ttl;
    cudaGetSymbolAddress((void**)&Phi,  g_Phi);
    cudaGetSymbolAddress((void**)&Plo,  g_Plo);
    cudaGetSymbolAddress((void**)&VAh,  g_VAh);
    cudaGetSymbolAddress((void**)&VAl,  g_VAl);
    cudaGetSymbolAddress((void**)&VtAh, g_VtAh);
    cudaGetSymbolAddress((void**)&VtAl, g_VtAl);
    cudaGetSymbolAddress((void**)&VBh,  g_VBh);
    cudaGetSymbolAddress((void**)&VBl,  g_VBl);
    cudaGetSymbolAddress((void**)&VtBh, g_VtBh);
    cudaGetSymbolAddress((void**)&VtBl, g_VtBl);
    cudaGetSymbolAddress((void**)&Tth,  g_Tth);
    cudaGetSymbolAddress((void**)&Ttl,  g_Ttl);

    // 1) scale + row norms
    {
        size_t rows = (size_t)BH * Nn;
        int blocks = (int)((rows * 32 + 255) / 256);
        scale_qnorm_kernel<<<blocks, 256>>>(Q, Qs, qn);
    }
    // 2) im2col
    {
        size_t total = (size_t)BH * MM * PATCH;
        im2col_kernel<<<(int)((total + 255) / 256), 256>>>(Qs, patch);
    }
    // 3) landmark conv GEMM: [25088,1024]x[1024,64]
    {
        dim3 grid(ceil_div(HD, BNt), ceil_div(BH * MM, BMt), 1);
        gemm_kernel<0, 0><<<grid, 256>>>(patch, w_land, Ql, nullptr, nullptr,
                                         BH * MM, HD, PATCH, PATCH, HD, HD,
                                         0, 0, 0, 0, 0);
    }
    // 4) LN + GELU + transpose + norms
    ln_gelu_kernel<<<BH * MM, 64>>>(Ql, QlT, lnn, gamma, beta);
    // 5) k2 = gauss(Ql,Ql)
    {
        dim3 grid(ceil_div(MM, BNt), ceil_div(MM, BMt), BH);
        gemm_kernel<1, 0><<<grid, 256>>>(Ql, QlT, k2, lnn, lnn,
                                         MM, MM, HD, HD, MM, MM,
                                         (size_t)MM * HD, (size_t)HD * MM, (size_t)MM * MM,
                                         MM, MM);
    }
    // 6) Newton init scale + split prep
    nscale_kernel<<<BH, 256>>>(k2, scale);
    {
        size_t total = (size_t)BH * PD2;
        newton_prep_kernel<<<(int)((total + 255) / 256), 256>>>(k2, scale,
                                                                Phi, Plo, VAh, VAl, VtAh, VtAl);
    }
    // 7) Newton-Schulz on tensor cores (mma.sync bf16, split precision)
    {
        __nv_bfloat16 *cVh = VAh, *cVl = VAl, *cVth = VtAh, *cVtl = VtAl;
        __nv_bfloat16 *nVh = VBh, *nVl = VBl, *nVth = VtBh, *nVtl = VtBl;
        dim3 grid(PD / 128, PD / 128, BH);
        for (int it = 0; it < NEWTON_ITERS; it++) {
            if (it < CHEAP_ITERS) {
                newton_wmma_kernel<1, 0><<<grid, 256>>>(Phi, Plo, cVth, cVtl,
                                                        Tth, Ttl, nullptr, nullptr);
                newton_wmma_kernel<1, 1><<<grid, 256>>>(cVh, cVl, Tth, Ttl,
                                                        nVh, nVl, nVth, nVtl);
            } else {
                newton_wmma_kernel<3, 0><<<grid, 256>>>(Phi, Plo, cVth, cVtl,
                                                        Tth, Ttl, nullptr, nullptr);
                newton_wmma_kernel<3, 1><<<grid, 256>>>(cVh, cVl, Tth, Ttl,
                                                        nVh, nVl, nVth, nVtl);
            }
            __nv_bfloat16* t;
            t = cVh;  cVh = nVh;   nVh = t;
            t = cVl;  cVl = nVl;   nVl = t;
            t = cVth; cVth = nVth; nVth = t;
            t = cVtl; cVtl = nVtl; nVtl = t;
        }
        size_t total = (size_t)BH * MM * MM;
        newton_merge_kernel<<<(int)((total + 255) / 256), 256>>>(cVh, cVl, Va);
    }
    // 8) k1 = gauss(Qs, Ql)
    {
        dim3 grid(ceil_div(MM, BNt), ceil_div(Nn, BMt), BH);
        gemm_kernel<1, 0><<<grid, 256>>>(Qs, QlT, k1, qn, lnn,
                                         Nn, MM, HD, HD, MM, MM,
                                         (size_t)Nn * HD, (size_t)HD * MM, (size_t)Nn * MM,
                                         Nn, MM);
    }
    // 9) Z = k1^T @ V
    {
        dim3 grid(ceil_div(HD, BNt), ceil_div(MM, BMt), BH);
        gemm_kernel<0, 1><<<grid, 256>>>(k1, V, Z, nullptr, nullptr,
                                         MM, HD, Nn, MM, HD, HD,
                                         (size_t)Nn * MM, (size_t)Nn * HD, (size_t)MM * HD,
                                         0, 0);
    }
    // 10) Y = inv @ Z
    {
        dim3 grid(ceil_div(HD, BNt), ceil_div(MM, BMt), BH);
        gemm_kernel<0, 0><<<grid, 256>>>(Va, Z, Y, nullptr, nullptr,
                                         MM, HD, MM, MM, HD, HD,
                                         (size_t)MM * MM, (size_t)MM * HD, (size_t)MM * HD,
                                         0, 0);
    }
    // 11) depthwise conv residual -> d_out
    {
        dim3 grid(Hh, BH);
        dwconv_kernel<<<grid, 256>>>(V, conv_w, out);
    }
    // 12) d_out += k1 @ Y
    {
        dim3 grid(ceil_div(HD, BNt), ceil_div(Nn, BMt), BH);
        gemm_kernel<2, 0><<<grid, 256>>>(k1, Y, out, nullptr, nullptr,
                                         Nn, HD, MM, MM, HD, HD,
                                         (size_t)Nn * MM, (size_t)MM * HD, (size_t)Nn * HD,
                                         0, 0);
    }
    (void)in_sizes; (void)n_in; (void)out_size;
}

// round 12
// speedup vs baseline: 1.8454x; 1.5952x over previous
#include <cuda_runtime.h>
#include <cuda_bf16.h>
#include <math.h>
#include <stdint.h>

// ---------------- problem constants ----------------
#define Bb 16
#define NH 8
#define BH (Bb*NH)          // 128
#define Hh 56
#define Ww 56
#define Nn (Hh*Ww)          // 3136
#define HD 64
#define RATIO 4
#define HL (Hh/RATIO)       // 14
#define MM (HL*HL)          // 196 landmarks
#define MM2 ((size_t)MM*MM) // 38416
#define PATCH (RATIO*RATIO*HD) // 1024
#define NEWTON_ITERS 20
#define CHEAP_ITERS 16      // bf16x2 packed iterations; remaining 4 in fp32
#define LN_EPS 1e-5f
#define QSCALE 0.35355339059327373f   // 64^{-0.25}

typedef unsigned int u32;

// ---------------- device scratch ----------------
__device__ float g_Qs   [(size_t)BH*Nn*HD];
__device__ float g_qn   [(size_t)BH*Nn];
__device__ float g_patch[(size_t)BH*MM*PATCH];
__device__ float g_Ql   [(size_t)BH*MM*HD];
__device__ float g_QlT  [(size_t)BH*HD*MM];
__device__ float g_ln   [(size_t)BH*MM];
__device__ float g_k2   [(size_t)BH*MM2];
__device__ float g_scale[BH];
__device__ float g_Va   [(size_t)BH*MM2];
__device__ float g_Vb   [(size_t)BH*MM2];
__device__ float g_T    [(size_t)BH*MM2];
__device__ float g_k1   [(size_t)BH*Nn*MM];
__device__ float g_Z    [(size_t)BH*MM*HD];
__device__ float g_Y    [(size_t)BH*MM*HD];

// bf16 Newton state [BH][196][196]
__device__ __nv_bfloat16 g_Pb [(size_t)BH*MM2];
__device__ __nv_bfloat16 g_Vba[(size_t)BH*MM2];
__device__ __nv_bfloat16 g_Vbb[(size_t)BH*MM2];
__device__ __nv_bfloat16 g_Tb [(size_t)BH*MM2];

// ---------------- kernel: Qs = Q*s, qn = |row|^2 ----------------
__global__ __launch_bounds__(256) void scale_qnorm_kernel(const float* __restrict__ Q,
                                                          float* __restrict__ Qs,
                                                          float* __restrict__ qn) {
    size_t warp = ((size_t)blockIdx.x * blockDim.x + threadIdx.x) >> 5;
    int lane = threadIdx.x & 31;
    if (warp >= (size_t)BH * Nn) return;
    float2 v = ((const float2*)(Q + warp * HD))[lane];
    v.x *= QSCALE; v.y *= QSCALE;
    ((float2*)(Qs + warp * HD))[lane] = v;
    float ss = v.x * v.x + v.y * v.y;
    #pragma unroll
    for (int o = 16; o; o >>= 1) ss += __shfl_xor_sync(0xffffffffu, ss, o);
    if (lane == 0) qn[warp] = ss;
}

// ---------------- im2col ----------------
__global__ __launch_bounds__(256) void im2col_kernel(const float* __restrict__ Qs,
                                                     float* __restrict__ patch) {
    size_t idx = (size_t)blockIdx.x * blockDim.x + threadIdx.x;
    const size_t total = (size_t)BH * MM * PATCH;
    if (idx >= total) return;
    int ic = idx & (HD - 1);
    int e  = (int)((idx >> 6) & 15);
    size_t row = idx >> 10;
    int p  = (int)(row % MM);
    int bh = (int)(row / MM);
    int py = p / HL, px = p % HL;
    int dy = e >> 2, dx = e & 3;
    int y = py * RATIO + dy, x = px * RATIO + dx;
    patch[idx] = Qs[((size_t)bh * Nn + (size_t)y * Ww + x) * HD + ic];
}

// ---------------- scalar batched SGEMM (R2, proven) ----------------
// EPI: 0 C=AB, 1 C=exp(-0.5(r+c-2AB)), 2 C=2A-AB (lda==ldc), 3 C+=AB
#define BMt 64
#define BNt 64
#define BKt 16
template<int EPI, int TRA>
__global__ __launch_bounds__(256) void gemm_kernel(const float* __restrict__ A,
                                                   const float* __restrict__ B,
                                                   float* __restrict__ C,
                                                   const float* __restrict__ rAux,
                                                   const float* __restrict__ cAux,
                                                   int M, int N, int K,
                                                   int lda, int ldb, int ldc,
                                                   size_t sA, size_t sB, size_t sC,
                                                   int sRA, int sCA) {
    int bz = blockIdx.z;
    A += (size_t)bz * sA; B += (size_t)bz * sB; C += (size_t)bz * sC;
    if (EPI == 1) { rAux += (size_t)bz * sRA; cAux += (size_t)bz * sCA; }
    int m0 = blockIdx.y * BMt, n0 = blockIdx.x * BNt;
    __shared__ float As[BKt][BMt];
    __shared__ float Bs[BKt][BNt];
    int t = threadIdx.x;
    int tx = t & 15, ty = t >> 4;
    float acc[4][4] = {};
    for (int k0 = 0; k0 < K; k0 += BKt) {
        #pragma unroll
        for (int j = 0; j < 4; j++) {
            int idx = t + 256 * j;
            if (TRA == 0) {
                int kk = idx & 15, mm = idx >> 4;
                int gm = m0 + mm, gk = k0 + kk;
                As[kk][mm] = (gm < M && gk < K) ? A[(size_t)gm * lda + gk] : 0.f;
            } else {
                int mm = idx & 63, kk = idx >> 6;
                int gm = m0 + mm, gk = k0 + kk;
                As[kk][mm] = (gm < M && gk < K) ? A[(size_t)gk * lda + gm] : 0.f;
            }
            int nn = idx & 63, kk2 = idx >> 6;
            int gn = n0 + nn, gk2 = k0 + kk2;
            Bs[kk2][nn] = (gn < N && gk2 < K) ? B[(size_t)gk2 * ldb + gn] : 0.f;
        }
        __syncthreads();
        #pragma unroll
        for (int kk = 0; kk < BKt; kk++) {
            float a[4], b[4];
            #pragma unroll
            for (int i = 0; i < 4; i++) a[i] = As[kk][ty * 4 + i];
            #pragma unroll
            for (int j = 0; j < 4; j++) b[j] = Bs[kk][tx * 4 + j];
            #pragma unroll
            for (int i = 0; i < 4; i++)
                #pragma unroll
                for (int j = 0; j < 4; j++)
                    acc[i][j] += a[i] * b[j];
        }
        __syncthreads();
    }
    #pragma unroll
    for (int i = 0; i < 4; i++) {
        int gm = m0 + ty * 4 + i;
        if (gm >= M) continue;
        #pragma unroll
        for (int j = 0; j < 4; j++) {
            int gn = n0 + tx * 4 + j;
            if (gn >= N) continue;
            float v = acc[i][j];
            size_t off = (size_t)gm * ldc + gn;
            if (EPI == 0)      C[off] = v;
            else if (EPI == 1) C[off] = __expf(-0.5f * (rAux[gm] + cAux[gn] - 2.f * v));
            else if (EPI == 2) C[off] = 2.f * A[(size_t)gm * lda + gn] - v;
            else               C[off] += v;
        }
    }
}

// ---------------- packed bf16x2 batched GEMM (Newton cheap phase) ----------------
// All matrices [BH][196][196] bf16 row-major. D = A@B; EPI 0: C=D; EPI 2: C=2A-D.
// Tile 112x112, 224 threads, micro 4 rows x 7 bf16x2 (14 cols). N packed in pairs.
#define ASTR 114
#define BSTR 56
template<int EPI>
__global__ __launch_bounds__(224) void bgemm_kernel(const __nv_bfloat16* __restrict__ A,
                                                    const __nv_bfloat16* __restrict__ B,
                                                    __nv_bfloat16* __restrict__ C) {
    const int bh = blockIdx.z;
    const u32* pA = (const u32*)(A + (size_t)bh * MM2);
    const u32* pB = (const u32*)(B + (size_t)bh * MM2);
    u32* pC = (u32*)(C + (size_t)bh * MM2);
    const int m0 = blockIdx.y * 112, n0 = blockIdx.x * 112;

    __shared__ u32 As2[16][ASTR];   // A values duplicated into both bf16 halves
    __shared__ u32 Bs2[16][BSTR];   // B col-pairs

    const int tid = threadIdx.x;
    const int ty = tid >> 3, tx = tid & 7;   // 28 x 8
    const int mr = ty * 4;                   // 4 rows/thread
    const int nr = tx * 7;                   // 7 col-pairs/thread

    __nv_bfloat162 acc[4][7];
    #pragma unroll
    for (int i = 0; i < 4; i++)
        #pragma unroll
        for (int j = 0; j < 7; j++) acc[i][j] = __nv_bfloat162{__nv_bfloat16(0.f), __nv_bfloat16(0.f)};

    for (int kc = 0; kc < 13; kc++) {
        const int k0 = kc * 16;
        // A tile: 112 rows x 16 k (8 u32 pairs/row) -> dup-stored transposed [k][row]
        #pragma unroll
        for (int j = 0; j < 4; j++) {
            int i = tid + 224 * j;          // 0..895
            int kp = i & 7, row = i >> 3;
            int gm = m0 + row, gk = k0 + kp * 2;
            u32 v = 0;
            if (gm < MM && gk < MM) v = pA[gm * (MM/2) + (gk >> 1)];
            As2[kp * 2    ][row] = __byte_perm(v, v, 0x1010);
            As2[kp * 2 + 1][row] = __byte_perm(v, v, 0x3232);
        }
        // B tile: 16 k-rows x 56 col-pairs
        #pragma unroll
        for (int j = 0; j < 4; j++) {
            int i = tid + 224 * j;
            int cp = i % 56, kk = i / 56;
            int gk = k0 + kk, gn = n0 + cp * 2;
            u32 v = 0;
            if (gk < MM && gn < MM) v = pB[gk * (MM/2) + (gn >> 1)];
            Bs2[kk][cp] = v;
        }
        __syncthreads();
        #pragma unroll
        for (int kk = 0; kk < 16; kk++) {
            __nv_bfloat162 a[4], b[7];
            #pragma unroll
            for (int i = 0; i < 4; i++) a[i] = *(const __nv_bfloat162*)&As2[kk][mr + i];
            #pragma unroll
            for (int j = 0; j < 7; j++) b[j] = *(const __nv_bfloat162*)&Bs2[kk][nr + j];
            #pragma unroll
            for (int i = 0; i < 4; i++)
                #pragma unroll
                for (int j = 0; j < 7; j++)
                    acc[i][j] = __hfma2(a[i], b[j], acc[i][j]);
        }
        __syncthreads();
    }

    #pragma unroll
    for (int i = 0; i < 4; i++) {
        int gm = m0 + mr + i;
        if (gm >= MM) continue;
        #pragma unroll
        for (int j = 0; j < 7; j++) {
            int gn = n0 + (nr + j) * 2;
            if (gn >= MM) continue;
            __nv_bfloat162 d = acc[i][j];
            if (EPI == 2) {
                __nv_bfloat162 a2 = *(const __nv_bfloat162*)&pA[gm * (MM/2) + (gn >> 1)];
                d = __hsub2(__hadd2(a2, a2), d);
            }
            pC[gm * (MM/2) + (gn >> 1)] = *(u32*)&d;
        }
    }
}

// ---------------- Newton prep / convert ----------------
__global__ __launch_bounds__(256) void prep_bf16_kernel(const float* __restrict__ k2,
                                                        const float* __restrict__ scale,
                                                        __nv_bfloat16* __restrict__ Pb,
                                                        __nv_bfloat16* __restrict__ Vb) {
    size_t idx = (size_t)blockIdx.x * blockDim.x + threadIdx.x;
    if (idx >= (size_t)BH * MM2) return;
    int bh = (int)(idx / MM2);
    float p = k2[idx];
    Pb[idx] = __float2bfloat16(p);
    Vb[idx] = __float2bfloat16(p * scale[bh]);
}

__global__ __launch_bounds__(256) void b2f_kernel(const __nv_bfloat16* __restrict__ Vb,
                                                  float* __restrict__ Vf) {
    size_t idx = (size_t)blockIdx.x * blockDim.x + threadIdx.x;
    if (idx >= (size_t)BH * MM2) return;
    Vf[idx] = __bfloat162float(Vb[idx]);
}

// ---------------- LayerNorm + erf-GELU + transpose + norms ----------------
__global__ __launch_bounds__(64) void ln_gelu_kernel(float* __restrict__ Ql,
                                                     float* __restrict__ QlT,
                                                     float* __restrict__ lnn,
                                                     const float* __restrict__ gamma,
                                                     const float* __restrict__ beta) {
    int row = blockIdx.x;
    int t = threadIdx.x;
    __shared__ float sm[2];
    float x = Ql[(size_t)row * HD + t];

    float v = x;
    #pragma unroll
    for (int o = 16; o; o >>= 1) v += __shfl_xor_sync(0xffffffffu, v, o);
    if ((t & 31) == 0) sm[t >> 5] = v;
    __syncthreads();
    float mean = (sm[0] + sm[1]) * (1.f / HD);
    __syncthreads();

    float d = x - mean;
    v = d * d;
    #pragma unroll
    for (int o = 16; o; o >>= 1) v += __shfl_xor_sync(0xffffffffu, v, o);
    if ((t & 31) == 0) sm[t >> 5] = v;
    __syncthreads();
    float var = (sm[0] + sm[1]) * (1.f / HD);
    __syncthreads();

    float y = d * rsqrtf(var + LN_EPS) * gamma[t] + beta[t];
    float g = 0.5f * y * (1.f + erff(y * 0.70710678118654752f));

    Ql[(size_t)row * HD + t] = g;
    int bh = row / MM, p = row % MM;
    QlT[((size_t)bh * HD + t) * MM + p] = g;

    v = g * g;
    #pragma unroll
    for (int o = 16; o; o >>= 1) v += __shfl_xor_sync(0xffffffffu, v, o);
    if ((t & 31) == 0) sm[t >> 5] = v;
    __syncthreads();
    if (t == 0) lnn[row] = sm[0] + sm[1];
}

// ---------------- Newton init scale ----------------
__global__ __launch_bounds__(256) void nscale_kernel(const float* __restrict__ k2,
                                                     float* __restrict__ scale) {
    int bh = blockIdx.x;
    int t = threadIdx.x;
    float rs = 0.f;
    if (t < MM) {
        const float* r = k2 + (size_t)bh * MM2 + (size_t)t * MM;
        for (int j = 0; j < MM; j++) rs += r[j];
    }
    __shared__ float sm[256];
    sm[t] = rs;
    __syncthreads();
    for (int o = 128; o; o >>= 1) {
        if (t < o) sm[t] = fmaxf(sm[t], sm[t + o]);
        __syncthreads();
    }
    if (t == 0) scale[bh] = 1.f / (sm[0] * sm[0]);
}

// ---------------- depthwise 3x3 conv over heads ----------------
__global__ __launch_bounds__(256) void dwconv_kernel(const float* __restrict__ V,
                                                     const float* __restrict__ w,
                                                     float* __restrict__ out) {
    int bh = blockIdx.y;
    int y  = blockIdx.x;
    int h  = bh & (NH - 1);
    float wv[9];
    #pragma unroll
    for (int k = 0; k < 9; k++) wv[k] = w[k * NH + h];
    for (int idx = threadIdx.x; idx < Ww * HD; idx += blockDim.x) {
        int x = idx >> 6;
        int c = idx & (HD - 1);
        float acc = 0.f;
        #pragma unroll
        for (int dy = -1; dy <= 1; dy++) {
            int yy = y + dy;
            if (yy < 0 || yy >= Hh) continue;
            #pragma unroll
            for (int dx = -1; dx <= 1; dx++) {
                int xx = x + dx;
                if (xx < 0 || xx >= Ww) continue;
                acc += wv[(dy + 1) * 3 + (dx + 1)] *
                       V[((size_t)bh * Nn + (size_t)yy * Ww + xx) * HD + c];
            }
        }
        out[((size_t)bh * Nn + (size_t)y * Ww + x) * HD + c] = acc;
    }
}

// ---------------- host launch ----------------
static inline int ceil_div(int a, int b) { return (a + b - 1) / b; }

extern "C" void kernel_launch(void* const* d_in, const int* in_sizes, int n_in,
                              void* d_out, int out_size) {
    const float* Q      = (const float*)d_in[0];
    const float* V      = (const float*)d_in[1];
    const float* w_land = (const float*)d_in[2];
    const float* gamma  = (const float*)d_in[3];
    const float* beta   = (const float*)d_in[4];
    const float* conv_w = (const float*)d_in[5];
    float* out = (float*)d_out;

    float *Qs, *qn, *patch, *Ql, *QlT, *lnn, *k2, *scale, *Va, *Vb, *T, *k1, *Z, *Y;
    cudaGetSymbolAddress((void**)&Qs,    g_Qs);
    cudaGetSymbolAddress((void**)&qn,    g_qn);
    cudaGetSymbolAddress((void**)&patch, g_patch);
    cudaGetSymbolAddress((void**)&Ql,    g_Ql);
    cudaGetSymbolAddress((void**)&QlT,   g_QlT);
    cudaGetSymbolAddress((void**)&lnn,   g_ln);
    cudaGetSymbolAddress((void**)&k2,    g_k2);
    cudaGetSymbolAddress((void**)&scale, g_scale);
    cudaGetSymbolAddress((void**)&Va,    g_Va);
    cudaGetSymbolAddress((void**)&Vb,    g_Vb);
    cudaGetSymbolAddress((void**)&T,     g_T);
    cudaGetSymbolAddress((void**)&k1,    g_k1);
    cudaGetSymbolAddress((void**)&Z,     g_Z);
    cudaGetSymbolAddress((void**)&Y,     g_Y);

    __nv_bfloat16 *Pb, *Vba, *Vbb, *Tb;
    cudaGetSymbolAddress((void**)&Pb,  g_Pb);
    cudaGetSymbolAddress((void**)&Vba, g_Vba);
    cudaGetSymbolAddress((void**)&Vbb, g_Vbb);
    cudaGetSymbolAddress((void**)&Tb,  g_Tb);

    // 1) scale + row norms
    {
        size_t rows = (size_t)BH * Nn;
        int blocks = (int)((rows * 32 + 255) / 256);
        scale_qnorm_kernel<<<blocks, 256>>>(Q, Qs, qn);
    }
    // 2) im2col
    {
        size_t total = (size_t)BH * MM * PATCH;
        im2col_kernel<<<(int)((total + 255) / 256), 256>>>(Qs, patch);
    }
    // 3) landmark conv GEMM
    {
        dim3 grid(ceil_div(HD, BNt), ceil_div(BH * MM, BMt), 1);
        gemm_kernel<0, 0><<<grid, 256>>>(patch, w_land, Ql, nullptr, nullptr,
                                         BH * MM, HD, PATCH, PATCH, HD, HD,
                                         0, 0, 0, 0, 0);
    }
    // 4) LN + GELU + transpose + norms
    ln_gelu_kernel<<<BH * MM, 64>>>(Ql, QlT, lnn, gamma, beta);
    // 5) k2 = gauss(Ql,Ql)
    {
        dim3 grid(ceil_div(MM, BNt), ceil_div(MM, BMt), BH);
        gemm_kernel<1, 0><<<grid, 256>>>(Ql, QlT, k2, lnn, lnn,
                                         MM, MM, HD, HD, MM, MM,
                                         (size_t)MM * HD, (size_t)HD * MM, MM2,
                                         MM, MM);
    }
    // 6) Newton init
    nscale_kernel<<<BH, 256>>>(k2, scale);
    {
        size_t total = (size_t)BH * MM2;
        prep_bf16_kernel<<<(int)((total + 255) / 256), 256>>>(k2, scale, Pb, Vba);
    }
    // 7a) cheap phase: 16 iterations in packed bf16x2
    {
        __nv_bfloat16 *cur = Vba, *nxt = Vbb;
        dim3 grid(2, 2, BH);
        for (int it = 0; it < CHEAP_ITERS; it++) {
            bgemm_kernel<0><<<grid, 224>>>(Pb, cur, Tb);    // T = P@V
            bgemm_kernel<2><<<grid, 224>>>(cur, Tb, nxt);   // V' = 2V - V@T
            __nv_bfloat16* t = cur; cur = nxt; nxt = t;
        }
        // even count -> result in Vba
        size_t total = (size_t)BH * MM2;
        b2f_kernel<<<(int)((total + 255) / 256), 256>>>(cur, Va);
    }
    // 7b) accurate phase: 4 fp32 iterations
    {
        float *cur = Va, *nxt = Vb;
        dim3 grid(ceil_div(MM, BNt), ceil_div(MM, BMt), BH);
        for (int it = 0; it < NEWTON_ITERS - CHEAP_ITERS; it++) {
            gemm_kernel<0, 0><<<grid, 256>>>(k2, cur, T, nullptr, nullptr,
                                             MM, MM, MM, MM, MM, MM,
                                             MM2, MM2, MM2, 0, 0);
            gemm_kernel<2, 0><<<grid, 256>>>(cur, T, nxt, nullptr, nullptr,
                                             MM, MM, MM, MM, MM, MM,
                                             MM2, MM2, MM2, 0, 0);
            float* t = cur; cur = nxt; nxt = t;
        }
        // 4 iterations (even) -> result back in Va
    }
    // 8) k1 = gauss(Qs, Ql)
    {
        dim3 grid(ceil_div(MM, BNt), ceil_div(Nn, BMt), BH);
        gemm_kernel<1, 0><<<grid, 256>>>(Qs, QlT, k1, qn, lnn,
                                         Nn, MM, HD, HD, MM, MM,
                                         (size_t)Nn * HD, (size_t)HD * MM, (size_t)Nn * MM,
                                         Nn, MM);
    }
    // 9) Z = k1^T @ V
    {
        dim3 grid(ceil_div(HD, BNt), ceil_div(MM, BMt), BH);
        gemm_kernel<0, 1><<<grid, 256>>>(k1, V, Z, nullptr, nullptr,
                                         MM, HD, Nn, MM, HD, HD,
                                         (size_t)Nn * MM, (size_t)Nn * HD, (size_t)MM * HD,
                                         0, 0);
    }
    // 10) Y = inv @ Z
    {
        dim3 grid(ceil_div(HD, BNt), ceil_div(MM, BMt), BH);
        gemm_kernel<0, 0><<<grid, 256>>>(Va, Z, Y, nullptr, nullptr,
                                         MM, HD, MM, MM, HD, HD,
                                         MM2, (size_t)MM * HD, (size_t)MM * HD,
                                         0, 0);
    }
    // 11) depthwise conv residual -> d_out
    {
        dim3 grid(Hh, BH);
        dwconv_kernel<<<grid, 256>>>(V, conv_w, out);
    }
    // 12) d_out += k1 @ Y
    {
        dim3 grid(ceil_div(HD, BNt), ceil_div(Nn, BMt), BH);
        gemm_kernel<3, 0><<<grid, 256>>>(k1, Y, out, nullptr, nullptr,
                                         Nn, HD, MM, MM, HD, HD,
                                         (size_t)Nn * MM, (size_t)MM * HD, (size_t)Nn * HD,
                                         0, 0);
    }
    (void)in_sizes; (void)n_in; (void)out_size;
}

// round 13
// speedup vs baseline: 2.1901x; 1.1868x over previous
#include <cuda_runtime.h>
#include <cuda_bf16.h>
#include <math.h>
#include <stdint.h>

// ---------------- problem constants ----------------
#define Bb 16
#define NH 8
#define BH (Bb*NH)          // 128
#define Hh 56
#define Ww 56
#define Nn (Hh*Ww)          // 3136
#define HD 64
#define RATIO 4
#define HL (Hh/RATIO)       // 14
#define MM (HL*HL)          // 196 landmarks
#define MM2 ((size_t)MM*MM) // 38416
#define PATCH (RATIO*RATIO*HD) // 1024
#define CHEAP_ITERS 14      // bf16x2 packed iterations
#define FP32_ITERS 2        // fp32 cleanup iterations (quadratic residual squash)
#define LN_EPS 1e-5f
#define QSCALE 0.35355339059327373f   // 64^{-0.25}

typedef unsigned int u32;

// ---------------- device scratch ----------------
__device__ float g_Qs   [(size_t)BH*Nn*HD];
__device__ float g_qn   [(size_t)BH*Nn];
__device__ float g_patch[(size_t)BH*MM*PATCH];
__device__ float g_Ql   [(size_t)BH*MM*HD];
__device__ float g_QlT  [(size_t)BH*HD*MM];
__device__ float g_ln   [(size_t)BH*MM];
__device__ float g_k2   [(size_t)BH*MM2];
__device__ float g_scale[BH];
__device__ float g_Va   [(size_t)BH*MM2];
__device__ float g_Vb   [(size_t)BH*MM2];
__device__ float g_T    [(size_t)BH*MM2];
__device__ float g_k1   [(size_t)BH*Nn*MM];
__device__ float g_Z    [(size_t)BH*MM*HD];
__device__ float g_Y    [(size_t)BH*MM*HD];

// bf16 Newton state [BH][196][196]
__device__ __nv_bfloat16 g_Pb [(size_t)BH*MM2];
__device__ __nv_bfloat16 g_Vba[(size_t)BH*MM2];
__device__ __nv_bfloat16 g_Vbb[(size_t)BH*MM2];
__device__ __nv_bfloat16 g_Tb [(size_t)BH*MM2];

// ---------------- kernel: Qs = Q*s, qn = |row|^2 ----------------
__global__ __launch_bounds__(256) void scale_qnorm_kernel(const float* __restrict__ Q,
                                                          float* __restrict__ Qs,
                                                          float* __restrict__ qn) {
    size_t warp = ((size_t)blockIdx.x * blockDim.x + threadIdx.x) >> 5;
    int lane = threadIdx.x & 31;
    if (warp >= (size_t)BH * Nn) return;
    float2 v = ((const float2*)(Q + warp * HD))[lane];
    v.x *= QSCALE; v.y *= QSCALE;
    ((float2*)(Qs + warp * HD))[lane] = v;
    float ss = v.x * v.x + v.y * v.y;
    #pragma unroll
    for (int o = 16; o; o >>= 1) ss += __shfl_xor_sync(0xffffffffu, ss, o);
    if (lane == 0) qn[warp] = ss;
}

// ---------------- im2col ----------------
__global__ __launch_bounds__(256) void im2col_kernel(const float* __restrict__ Qs,
                                                     float* __restrict__ patch) {
    size_t idx = (size_t)blockIdx.x * blockDim.x + threadIdx.x;
    const size_t total = (size_t)BH * MM * PATCH;
    if (idx >= total) return;
    int ic = idx & (HD - 1);
    int e  = (int)((idx >> 6) & 15);
    size_t row = idx >> 10;
    int p  = (int)(row % MM);
    int bh = (int)(row / MM);
    int py = p / HL, px = p % HL;
    int dy = e >> 2, dx = e & 3;
    int y = py * RATIO + dy, x = px * RATIO + dx;
    patch[idx] = Qs[((size_t)bh * Nn + (size_t)y * Ww + x) * HD + ic];
}

// ---------------- scalar batched SGEMM (proven) ----------------
// EPI: 0 C=AB, 1 C=exp(-0.5(r+c-2AB)), 2 C=2A-AB (lda==ldc), 3 C+=AB
#define BMt 64
#define BNt 64
#define BKt 16
template<int EPI, int TRA>
__global__ __launch_bounds__(256) void gemm_kernel(const float* __restrict__ A,
                                                   const float* __restrict__ B,
                                                   float* __restrict__ C,
                                                   const float* __restrict__ rAux,
                                                   const float* __restrict__ cAux,
                                                   int M, int N, int K,
                                                   int lda, int ldb, int ldc,
                                                   size_t sA, size_t sB, size_t sC,
                                                   int sRA, int sCA) {
    int bz = blockIdx.z;
    A += (size_t)bz * sA; B += (size_t)bz * sB; C += (size_t)bz * sC;
    if (EPI == 1) { rAux += (size_t)bz * sRA; cAux += (size_t)bz * sCA; }
    int m0 = blockIdx.y * BMt, n0 = blockIdx.x * BNt;
    __shared__ float As[BKt][BMt];
    __shared__ float Bs[BKt][BNt];
    int t = threadIdx.x;
    int tx = t & 15, ty = t >> 4;
    float acc[4][4] = {};
    for (int k0 = 0; k0 < K; k0 += BKt) {
        #pragma unroll
        for (int j = 0; j < 4; j++) {
            int idx = t + 256 * j;
            if (TRA == 0) {
                int kk = idx & 15, mm = idx >> 4;
                int gm = m0 + mm, gk = k0 + kk;
                As[kk][mm] = (gm < M && gk < K) ? A[(size_t)gm * lda + gk] : 0.f;
            } else {
                int mm = idx & 63, kk = idx >> 6;
                int gm = m0 + mm, gk = k0 + kk;
                As[kk][mm] = (gm < M && gk < K) ? A[(size_t)gk * lda + gm] : 0.f;
            }
            int nn = idx & 63, kk2 = idx >> 6;
            int gn = n0 + nn, gk2 = k0 + kk2;
            Bs[kk2][nn] = (gn < N && gk2 < K) ? B[(size_t)gk2 * ldb + gn] : 0.f;
        }
        __syncthreads();
        #pragma unroll
        for (int kk = 0; kk < BKt; kk++) {
            float a[4], b[4];
            #pragma unroll
            for (int i = 0; i < 4; i++) a[i] = As[kk][ty * 4 + i];
            #pragma unroll
            for (int j = 0; j < 4; j++) b[j] = Bs[kk][tx * 4 + j];
            #pragma unroll
            for (int i = 0; i < 4; i++)
                #pragma unroll
                for (int j = 0; j < 4; j++)
                    acc[i][j] += a[i] * b[j];
        }
        __syncthreads();
    }
    #pragma unroll
    for (int i = 0; i < 4; i++) {
        int gm = m0 + ty * 4 + i;
        if (gm >= M) continue;
        #pragma unroll
        for (int j = 0; j < 4; j++) {
            int gn = n0 + tx * 4 + j;
            if (gn >= N) continue;
            float v = acc[i][j];
            size_t off = (size_t)gm * ldc + gn;
            if (EPI == 0)      C[off] = v;
            else if (EPI == 1) C[off] = __expf(-0.5f * (rAux[gm] + cAux[gn] - 2.f * v));
            else if (EPI == 2) C[off] = 2.f * A[(size_t)gm * lda + gn] - v;
            else               C[off] += v;
        }
    }
}

// ---------------- packed bf16x2 batched GEMM (Newton cheap phase) ----------------
// All matrices [BH][196][196] bf16 row-major. D = A@B; EPI 0: C=D; EPI 2: C=2A-D.
// Tile 112x112, 224 threads, micro 4 rows x 7 bf16x2 (14 cols).
#define ASTR 114   // u32 stride: even -> rows 8B aligned for LDS.64 pairs
#define BSTR 56
template<int EPI>
__global__ __launch_bounds__(224) void bgemm_kernel(const __nv_bfloat16* __restrict__ A,
                                                    const __nv_bfloat16* __restrict__ B,
                                                    __nv_bfloat16* __restrict__ C) {
    const int bh = blockIdx.z;
    const u32* pA = (const u32*)(A + (size_t)bh * MM2);
    const u32* pB = (const u32*)(B + (size_t)bh * MM2);
    u32* pC = (u32*)(C + (size_t)bh * MM2);
    const int m0 = blockIdx.y * 112, n0 = blockIdx.x * 112;

    __shared__ u32 As2[16][ASTR];   // A values duplicated into both bf16 halves
    __shared__ u32 Bs2[16][BSTR];   // B col-pairs

    const int tid = threadIdx.x;
    const int ty = tid >> 3, tx = tid & 7;   // 28 x 8
    const int mr = ty * 4;                   // 4 rows/thread (16B-aligned u32 base)
    const int nr = tx * 7;                   // 7 col-pairs/thread

    __nv_bfloat162 acc[4][7];
    #pragma unroll
    for (int i = 0; i < 4; i++)
        #pragma unroll
        for (int j = 0; j < 7; j++) acc[i][j] = __nv_bfloat162{__nv_bfloat16(0.f), __nv_bfloat16(0.f)};

    for (int kc = 0; kc < 13; kc++) {
        const int k0 = kc * 16;
        // A tile: 112 rows x 16 k (8 u32 pairs/row) -> dup-stored transposed [k][row]
        #pragma unroll
        for (int j = 0; j < 4; j++) {
            int i = tid + 224 * j;          // 0..895
            int kp = i & 7, row = i >> 3;
            int gm = m0 + row, gk = k0 + kp * 2;
            u32 v = 0;
            if (gm < MM && gk < MM) v = pA[gm * (MM/2) + (gk >> 1)];
            As2[kp * 2    ][row] = __byte_perm(v, v, 0x1010);
            As2[kp * 2 + 1][row] = __byte_perm(v, v, 0x3232);
        }
        // B tile: 16 k-rows x 56 col-pairs
        #pragma unroll
        for (int j = 0; j < 4; j++) {
            int i = tid + 224 * j;
            int cp = i % 56, kk = i / 56;
            int gk = k0 + kk, gn = n0 + cp * 2;
            u32 v = 0;
            if (gk < MM && gn < MM) v = pB[gk * (MM/2) + (gn >> 1)];
            Bs2[kk][cp] = v;
        }
        __syncthreads();
        #pragma unroll
        for (int kk = 0; kk < 16; kk++) {
            // A fragment: 2x LDS.64 (ASTR even -> 8B alignment guaranteed)
            uint2 a01 = *(const uint2*)&As2[kk][mr];
            uint2 a23 = *(const uint2*)&As2[kk][mr + 2];
            __nv_bfloat162 a[4];
            a[0] = *(__nv_bfloat162*)&a01.x;
            a[1] = *(__nv_bfloat162*)&a01.y;
            a[2] = *(__nv_bfloat162*)&a23.x;
            a[3] = *(__nv_bfloat162*)&a23.y;
            __nv_bfloat162 b[7];
            #pragma unroll
            for (int j = 0; j < 7; j++) b[j] = *(const __nv_bfloat162*)&Bs2[kk][nr + j];
            #pragma unroll
            for (int i = 0; i < 4; i++)
                #pragma unroll
                for (int j = 0; j < 7; j++)
                    acc[i][j] = __hfma2(a[i], b[j], acc[i][j]);
        }
        __syncthreads();
    }

    #pragma unroll
    for (int i = 0; i < 4; i++) {
        int gm = m0 + mr + i;
        if (gm >= MM) continue;
        #pragma unroll
        for (int j = 0; j < 7; j++) {
            int gn = n0 + (nr + j) * 2;
            if (gn >= MM) continue;
            __nv_bfloat162 d = acc[i][j];
            if (EPI == 2) {
                __nv_bfloat162 a2 = *(const __nv_bfloat162*)&pA[gm * (MM/2) + (gn >> 1)];
                d = __hsub2(__hadd2(a2, a2), d);
            }
            pC[gm * (MM/2) + (gn >> 1)] = *(u32*)&d;
        }
    }
}

// ---------------- Newton prep / convert ----------------
__global__ __launch_bounds__(256) void prep_bf16_kernel(const float* __restrict__ k2,
                                                        const float* __restrict__ scale,
                                                        __nv_bfloat16* __restrict__ Pb,
                                                        __nv_bfloat16* __restrict__ Vb) {
    size_t idx = (size_t)blockIdx.x * blockDim.x + threadIdx.x;
    if (idx >= (size_t)BH * MM2) return;
    int bh = (int)(idx / MM2);
    float p = k2[idx];
    Pb[idx] = __float2bfloat16(p);
    Vb[idx] = __float2bfloat16(p * scale[bh]);
}

__global__ __launch_bounds__(256) void b2f_kernel(const __nv_bfloat16* __restrict__ Vb,
                                                  float* __restrict__ Vf) {
    size_t idx = (size_t)blockIdx.x * blockDim.x + threadIdx.x;
    if (idx >= (size_t)BH * MM2) return;
    Vf[idx] = __bfloat162float(Vb[idx]);
}

// ---------------- LayerNorm + erf-GELU + transpose + norms ----------------
__global__ __launch_bounds__(64) void ln_gelu_kernel(float* __restrict__ Ql,
                                                     float* __restrict__ QlT,
                                                     float* __restrict__ lnn,
                                                     const float* __restrict__ gamma,
                                                     const float* __restrict__ beta) {
    int row = blockIdx.x;
    int t = threadIdx.x;
    __shared__ float sm[2];
    float x = Ql[(size_t)row * HD + t];

    float v = x;
    #pragma unroll
    for (int o = 16; o; o >>= 1) v += __shfl_xor_sync(0xffffffffu, v, o);
    if ((t & 31) == 0) sm[t >> 5] = v;
    __syncthreads();
    float mean = (sm[0] + sm[1]) * (1.f / HD);
    __syncthreads();

    float d = x - mean;
    v = d * d;
    #pragma unroll
    for (int o = 16; o; o >>= 1) v += __shfl_xor_sync(0xffffffffu, v, o);
    if ((t & 31) == 0) sm[t >> 5] = v;
    __syncthreads();
    float var = (sm[0] + sm[1]) * (1.f / HD);
    __syncthreads();

    float y = d * rsqrtf(var + LN_EPS) * gamma[t] + beta[t];
    float g = 0.5f * y * (1.f + erff(y * 0.70710678118654752f));

    Ql[(size_t)row * HD + t] = g;
    int bh = row / MM, p = row % MM;
    QlT[((size_t)bh * HD + t) * MM + p] = g;

    v = g * g;
    #pragma unroll
    for (int o = 16; o; o >>= 1) v += __shfl_xor_sync(0xffffffffu, v, o);
    if ((t & 31) == 0) sm[t >> 5] = v;
    __syncthreads();
    if (t == 0) lnn[row] = sm[0] + sm[1];
}

// ---------------- Newton init scale ----------------
__global__ __launch_bounds__(256) void nscale_kernel(const float* __restrict__ k2,
                                                     float* __restrict__ scale) {
    int bh = blockIdx.x;
    int t = threadIdx.x;
    float rs = 0.f;
    if (t < MM) {
        const float* r = k2 + (size_t)bh * MM2 + (size_t)t * MM;
        for (int j = 0; j < MM; j++) rs += r[j];
    }
    __shared__ float sm[256];
    sm[t] = rs;
    __syncthreads();
    for (int o = 128; o; o >>= 1) {
        if (t < o) sm[t] = fmaxf(sm[t], sm[t + o]);
        __syncthreads();
    }
    if (t == 0) scale[bh] = 1.f / (sm[0] * sm[0]);
}

// ---------------- depthwise 3x3 conv over heads ----------------
__global__ __launch_bounds__(256) void dwconv_kernel(const float* __restrict__ V,
                                                     const float* __restrict__ w,
                                                     float* __restrict__ out) {
    int bh = blockIdx.y;
    int y  = blockIdx.x;
    int h  = bh & (NH - 1);
    float wv[9];
    #pragma unroll
    for (int k = 0; k < 9; k++) wv[k] = w[k * NH + h];
    for (int idx = threadIdx.x; idx < Ww * HD; idx += blockDim.x) {
        int x = idx >> 6;
        int c = idx & (HD - 1);
        float acc = 0.f;
        #pragma unroll
        for (int dy = -1; dy <= 1; dy++) {
            int yy = y + dy;
            if (yy < 0 || yy >= Hh) continue;
            #pragma unroll
            for (int dx = -1; dx <= 1; dx++) {
                int xx = x + dx;
                if (xx < 0 || xx >= Ww) continue;
                acc += wv[(dy + 1) * 3 + (dx + 1)] *
                       V[((size_t)bh * Nn + (size_t)yy * Ww + xx) * HD + c];
            }
        }
        out[((size_t)bh * Nn + (size_t)y * Ww + x) * HD + c] = acc;
    }
}

// ---------------- host launch ----------------
static inline int ceil_div(int a, int b) { return (a + b - 1) / b; }

extern "C" void kernel_launch(void* const* d_in, const int* in_sizes, int n_in,
                              void* d_out, int out_size) {
    const float* Q      = (const float*)d_in[0];
    const float* V      = (const float*)d_in[1];
    const float* w_land = (const float*)d_in[2];
    const float* gamma  = (const float*)d_in[3];
    const float* beta   = (const float*)d_in[4];
    const float* conv_w = (const float*)d_in[5];
    float* out = (float*)d_out;

    float *Qs, *qn, *patch, *Ql, *QlT, *lnn, *k2, *scale, *Va, *Vb, *T, *k1, *Z, *Y;
    cudaGetSymbolAddress((void**)&Qs,    g_Qs);
    cudaGetSymbolAddress((void**)&qn,    g_qn);
    cudaGetSymbolAddress((void**)&patch, g_patch);
    cudaGetSymbolAddress((void**)&Ql,    g_Ql);
    cudaGetSymbolAddress((void**)&QlT,   g_QlT);
    cudaGetSymbolAddress((void**)&lnn,   g_ln);
    cudaGetSymbolAddress((void**)&k2,    g_k2);
    cudaGetSymbolAddress((void**)&scale, g_scale);
    cudaGetSymbolAddress((void**)&Va,    g_Va);
    cudaGetSymbolAddress((void**)&Vb,    g_Vb);
    cudaGetSymbolAddress((void**)&T,     g_T);
    cudaGetSymbolAddress((void**)&k1,    g_k1);
    cudaGetSymbolAddress((void**)&Z,     g_Z);
    cudaGetSymbolAddress((void**)&Y,     g_Y);

    __nv_bfloat16 *Pb, *Vba, *Vbb, *Tb;
    cudaGetSymbolAddress((void**)&Pb,  g_Pb);
    cudaGetSymbolAddress((void**)&Vba, g_Vba);
    cudaGetSymbolAddress((void**)&Vbb, g_Vbb);
    cudaGetSymbolAddress((void**)&Tb,  g_Tb);

    // 1) scale + row norms
    {
        size_t rows = (size_t)BH * Nn;
        int blocks = (int)((rows * 32 + 255) / 256);
        scale_qnorm_kernel<<<blocks, 256>>>(Q, Qs, qn);
    }
    // 2) im2col
    {
        size_t total = (size_t)BH * MM * PATCH;
        im2col_kernel<<<(int)((total + 255) / 256), 256>>>(Qs, patch);
    }
    // 3) landmark conv GEMM
    {
        dim3 grid(ceil_div(HD, BNt), ceil_div(BH * MM, BMt), 1);
        gemm_kernel<0, 0><<<grid, 256>>>(patch, w_land, Ql, nullptr, nullptr,
                                         BH * MM, HD, PATCH, PATCH, HD, HD,
                                         0, 0, 0, 0, 0);
    }
    // 4) LN + GELU + transpose + norms
    ln_gelu_kernel<<<BH * MM, 64>>>(Ql, QlT, lnn, gamma, beta);
    // 5) k2 = gauss(Ql,Ql)
    {
        dim3 grid(ceil_div(MM, BNt), ceil_div(MM, BMt), BH);
        gemm_kernel<1, 0><<<grid, 256>>>(Ql, QlT, k2, lnn, lnn,
                                         MM, MM, HD, HD, MM, MM,
                                         (size_t)MM * HD, (size_t)HD * MM, MM2,
                                         MM, MM);
    }
    // 6) Newton init
    nscale_kernel<<<BH, 256>>>(k2, scale);
    {
        size_t total = (size_t)BH * MM2;
        prep_bf16_kernel<<<(int)((total + 255) / 256), 256>>>(k2, scale, Pb, Vba);
    }
    // 7a) cheap phase: packed bf16x2 iterations
    {
        __nv_bfloat16 *cur = Vba, *nxt = Vbb;
        dim3 grid(2, 2, BH);
        for (int it = 0; it < CHEAP_ITERS; it++) {
            bgemm_kernel<0><<<grid, 224>>>(Pb, cur, Tb);    // T = P@V
            bgemm_kernel<2><<<grid, 224>>>(cur, Tb, nxt);   // V' = 2V - V@T
            __nv_bfloat16* t = cur; cur = nxt; nxt = t;
        }
        // even count -> result in Vba
        size_t total = (size_t)BH * MM2;
        b2f_kernel<<<(int)((total + 255) / 256), 256>>>(cur, Va);
    }
    // 7b) accurate phase: fp32 iterations
    {
        float *cur = Va, *nxt = Vb;
        dim3 grid(ceil_div(MM, BNt), ceil_div(MM, BMt), BH);
        for (int it = 0; it < FP32_ITERS; it++) {
            gemm_kernel<0, 0><<<grid, 256>>>(k2, cur, T, nullptr, nullptr,
                                             MM, MM, MM, MM, MM, MM,
                                             MM2, MM2, MM2, 0, 0);
            gemm_kernel<2, 0><<<grid, 256>>>(cur, T, nxt, nullptr, nullptr,
                                             MM, MM, MM, MM, MM, MM,
                                             MM2, MM2, MM2, 0, 0);
            float* t = cur; cur = nxt; nxt = t;
        }
        // even count -> result back in Va
    }
    // 8) k1 = gauss(Qs, Ql)
    {
        dim3 grid(ceil_div(MM, BNt), ceil_div(Nn, BMt), BH);
        gemm_kernel<1, 0><<<grid, 256>>>(Qs, QlT, k1, qn, lnn,
                                         Nn, MM, HD, HD, MM, MM,
                                         (size_t)Nn * HD, (size_t)HD * MM, (size_t)Nn * MM,
                                         Nn, MM);
    }
    // 9) Z = k1^T @ V
    {
        dim3 grid(ceil_div(HD, BNt), ceil_div(MM, BMt), BH);
        gemm_kernel<0, 1><<<grid, 256>>>(k1, V, Z, nullptr, nullptr,
                                         MM, HD, Nn, MM, HD, HD,
                                         (size_t)Nn * MM, (size_t)Nn * HD, (size_t)MM * HD,
                                         0, 0);
    }
    // 10) Y = inv @ Z
    {
        dim3 grid(ceil_div(HD, BNt), ceil_div(MM, BMt), BH);
        gemm_kernel<0, 0><<<grid, 256>>>(Va, Z, Y, nullptr, nullptr,
                                         MM, HD, MM, MM, HD, HD,
                                         MM2, (size_t)MM * HD, (size_t)MM * HD,
                                         0, 0);
    }
    // 11) depthwise conv residual -> d_out
    {
        dim3 grid(Hh, BH);
        dwconv_kernel<<<grid, 256>>>(V, conv_w, out);
    }
    // 12) d_out += k1 @ Y
    {
        dim3 grid(ceil_div(HD, BNt), ceil_div(Nn, BMt), BH);
        gemm_kernel<3, 0><<<grid, 256>>>(k1, Y, out, nullptr, nullptr,
                                         Nn, HD, MM, MM, HD, HD,
                                         (size_t)Nn * MM, (size_t)MM * HD, (size_t)Nn * HD,
                                         0, 0);
    }
    (void)in_sizes; (void)n_in; (void)out_size;
}